// round 4
// baseline (speedup 1.0000x reference)
#include <cuda_runtime.h>

typedef unsigned long long u64;

#define TOKENS    64
#define NTHREADS  256
#define IN_DIM    256
#define HDIM      64
#define NTASK     2
#define NEXP      12

#define XS_STRIDE 260
#define HS_STRIDE 66

// smem partition sizes (floats)
#define XS_SZ   (TOKENS * XS_STRIDE)   // 16640
#define W_SZ    (IN_DIM * HDIM)        // 16384
#define HS_SZ   (TOKENS * HS_STRIDE)   // 4224
#define GS_SZ   (TOKENS * 16)          // 1024
#define B_SZ    (HDIM)                 // 64
#define SMEM_FLOATS (XS_SZ + W_SZ + 2*HS_SZ + GS_SZ + B_SZ)
#define SMEM_BYTES  (SMEM_FLOATS * 4)

__device__ __forceinline__ u64 ffma2(u64 a, u64 b, u64 c) {
    u64 d;
    asm("fma.rn.f32x2 %0, %1, %2, %3;" : "=l"(d) : "l"(a), "l"(b), "l"(c));
    return d;
}
__device__ __forceinline__ u64 dup2(float x) {
    u64 d;
    asm("mov.b64 %0, {%1, %1};" : "=l"(d) : "f"(x));
    return d;
}
__device__ __forceinline__ float2 unpack2(u64 v) {
    float2 r;
    asm("mov.b64 {%0, %1}, %2;" : "=f"(r.x), "=f"(r.y) : "l"(v));
    return r;
}

// [2 rows x 8 cols] register tile GEMM over K, A rows from smem (contiguous k),
// W panel in smem row-major [K][64]. acc = packed f32x2 over column pairs.
template<int K>
__device__ __forceinline__ void gemm_tile(const float* __restrict__ a0p,
                                          const float* __restrict__ a1p,
                                          const float* __restrict__ Wsm,
                                          int c0, u64 acc[2][4]) {
    #pragma unroll 8
    for (int k = 0; k < K; k++) {
        u64 aa0 = dup2(a0p[k]);
        u64 aa1 = dup2(a1p[k]);
        const u64* wp = (const u64*)(Wsm + k * HDIM + c0);
        #pragma unroll
        for (int i = 0; i < 4; i++) {
            u64 w = wp[i];
            acc[0][i] = ffma2(aa0, w, acc[0][i]);
            acc[1][i] = ffma2(aa1, w, acc[1][i]);
        }
    }
}

__global__ void __launch_bounds__(NTHREADS, 1)
mmoe_kernel(const float* __restrict__ X,
            const float* __restrict__ Wt1, const float* __restrict__ bt1,
            const float* __restrict__ Wt2, const float* __restrict__ bt2,
            const float* __restrict__ Wt3, const float* __restrict__ bt3,
            const float* __restrict__ Ws1, const float* __restrict__ bs1,
            const float* __restrict__ Ws2, const float* __restrict__ bs2,
            const float* __restrict__ Ws3, const float* __restrict__ bs3,
            const float* __restrict__ Wg,  const float* __restrict__ bg,
            float* __restrict__ out)
{
    extern __shared__ float smem[];
    float* Xs  = smem;               // [64][260]
    float* Wsm = Xs + XS_SZ;         // weight panel (max 256x64)
    float* h1s = Wsm + W_SZ;         // [64][66]
    float* h2s = h1s + HS_SZ;        // [64][66]
    float* gs  = h2s + HS_SZ;        // [64][16] gate logits -> gates
    float* bsm = gs + GS_SZ;         // [64] bias

    const int tid = threadIdx.x;
    const int blk = blockIdx.x;
    const float* Xblk = X + (size_t)blk * TOKENS * IN_DIM;

    // ---- load X tile (float4, coalesced) ----
    for (int i = tid; i < TOKENS * (IN_DIM / 4); i += NTHREADS) {
        int row = i >> 6;            // IN_DIM/4 = 64 f4 per row
        int c4  = i & 63;
        float4 v = ((const float4*)Xblk)[(size_t)row * 64 + c4];
        *(float4*)&Xs[row * XS_STRIDE + c4 * 4] = v;
    }
    // ---- load Wg [2][256][8] into Wsm region ----
    for (int i = tid; i < (NTASK * IN_DIM * 8) / 4; i += NTHREADS)
        ((float4*)Wsm)[i] = ((const float4*)Wg)[i];
    __syncthreads();

    // ---- gate logits: each thread computes 4 of the 16 (t,e) logits for one token ----
    {
        int tok = tid >> 2, q = tid & 3;
        int t = q >> 1, e0 = (q & 1) * 4;
        const float* xr = &Xs[tok * XS_STRIDE];
        const float4* wg4 = (const float4*)&Wsm[t * (IN_DIM * 8) + e0];
        float a0 = 0.f, a1 = 0.f, a2 = 0.f, a3 = 0.f;
        #pragma unroll 8
        for (int k = 0; k < IN_DIM; k++) {
            float x = xr[k];
            float4 w = wg4[k * 2];
            a0 = fmaf(x, w.x, a0); a1 = fmaf(x, w.y, a1);
            a2 = fmaf(x, w.z, a2); a3 = fmaf(x, w.w, a3);
        }
        *(float4*)&gs[tok * 16 + q * 4] = make_float4(a0, a1, a2, a3);
    }
    __syncthreads();

    // ---- softmax per (token, task) over 8 experts ----
    if (tid < TOKENS * NTASK) {
        int tok = tid >> 1, t = tid & 1;
        float l[8];
        float m = -1e30f;
        #pragma unroll
        for (int i = 0; i < 8; i++) {
            l[i] = gs[tok * 16 + t * 8 + i] + bg[t * 8 + i];
            m = fmaxf(m, l[i]);
        }
        float s = 0.f;
        #pragma unroll
        for (int i = 0; i < 8; i++) { l[i] = expf(l[i] - m); s += l[i]; }
        float inv = 1.f / s;
        #pragma unroll
        for (int i = 0; i < 8; i++) gs[tok * 16 + t * 8 + i] = l[i] * inv;
    }
    // gs reads (combine) are separated from these writes by later barriers.

    const int ty = tid >> 3;          // 0..31
    const int tx = tid & 7;           // 0..7
    const int r0 = ty * 2, r1 = r0 + 1;
    const int c0 = tx * 8;

    float oacc[NTASK][2][8];
    #pragma unroll
    for (int t = 0; t < NTASK; t++)
        #pragma unroll
        for (int r = 0; r < 2; r++)
            #pragma unroll
            for (int c = 0; c < 8; c++) oacc[t][r][c] = 0.f;

    for (int e = 0; e < NEXP; e++) {
        const float *W1, *W2, *W3, *b1, *b2, *b3;
        if (e < 8) {
            W1 = Wt1 + e * IN_DIM * HDIM; b1 = bt1 + e * HDIM;
            W2 = Wt2 + e * HDIM * HDIM;   b2 = bt2 + e * HDIM;
            W3 = Wt3 + e * HDIM * HDIM;   b3 = bt3 + e * HDIM;
        } else {
            int s = e - 8;
            W1 = Ws1 + s * IN_DIM * HDIM; b1 = bs1 + s * HDIM;
            W2 = Ws2 + s * HDIM * HDIM;   b2 = bs2 + s * HDIM;
            W3 = Ws3 + s * HDIM * HDIM;   b3 = bs3 + s * HDIM;
        }

        // all prior readers of Wsm/bsm must be done before overwrite
        __syncthreads();

        // ===== Layer 1: [64x256] @ [256x64] =====
        for (int i = tid; i < (IN_DIM * HDIM) / 4; i += NTHREADS)
            ((float4*)Wsm)[i] = ((const float4*)W1)[i];
        if (tid < HDIM) bsm[tid] = b1[tid];
        __syncthreads();

        u64 acc[2][4] = {};
        gemm_tile<IN_DIM>(&Xs[r0 * XS_STRIDE], &Xs[r1 * XS_STRIDE], Wsm, c0, acc);

        #pragma unroll
        for (int r = 0; r < 2; r++) {
            int row = (r == 0) ? r0 : r1;
            #pragma unroll
            for (int i = 0; i < 4; i++) {
                float2 v = unpack2(acc[r][i]);
                int col = c0 + 2 * i;
                h1s[row * HS_STRIDE + col]     = fmaxf(v.x + bsm[col], 0.f);
                h1s[row * HS_STRIDE + col + 1] = fmaxf(v.y + bsm[col + 1], 0.f);
            }
        }
        __syncthreads();

        // ===== Layer 2: [64x64] @ [64x64] =====
        for (int i = tid; i < (HDIM * HDIM) / 4; i += NTHREADS)
            ((float4*)Wsm)[i] = ((const float4*)W2)[i];
        if (tid < HDIM) bsm[tid] = b2[tid];
        __syncthreads();

        u64 acc2[2][4] = {};
        gemm_tile<HDIM>(&h1s[r0 * HS_STRIDE], &h1s[r1 * HS_STRIDE], Wsm, c0, acc2);

        #pragma unroll
        for (int r = 0; r < 2; r++) {
            int row = (r == 0) ? r0 : r1;
            #pragma unroll
            for (int i = 0; i < 4; i++) {
                float2 v = unpack2(acc2[r][i]);
                int col = c0 + 2 * i;
                h2s[row * HS_STRIDE + col]     = fmaxf(v.x + bsm[col], 0.f);
                h2s[row * HS_STRIDE + col + 1] = fmaxf(v.y + bsm[col + 1], 0.f);
            }
        }
        __syncthreads();

        // ===== Layer 3: [64x64] @ [64x64] (no relu) =====
        for (int i = tid; i < (HDIM * HDIM) / 4; i += NTHREADS)
            ((float4*)Wsm)[i] = ((const float4*)W3)[i];
        if (tid < HDIM) bsm[tid] = b3[tid];
        __syncthreads();

        u64 acc3[2][4] = {};
        gemm_tile<HDIM>(&h2s[r0 * HS_STRIDE], &h2s[r1 * HS_STRIDE], Wsm, c0, acc3);

        float o[2][8];
        #pragma unroll
        for (int r = 0; r < 2; r++) {
            #pragma unroll
            for (int i = 0; i < 4; i++) {
                float2 v = unpack2(acc3[r][i]);
                int col = c0 + 2 * i;
                o[r][2 * i]     = v.x + bsm[col];
                o[r][2 * i + 1] = v.y + bsm[col + 1];
            }
        }

        // ===== gated combine (static oacc indexing; predicated gate weights) =====
        float gt0_r0, gt0_r1, gt1_r0, gt1_r1;
        if (e < 8) {
            int t = e >> 2, idx = e & 3;
            float v0 = gs[r0 * 16 + t * 8 + idx];
            float v1 = gs[r1 * 16 + t * 8 + idx];
            bool is0 = (t == 0);
            gt0_r0 = is0 ? v0 : 0.f;  gt0_r1 = is0 ? v1 : 0.f;
            gt1_r0 = is0 ? 0.f : v0;  gt1_r1 = is0 ? 0.f : v1;
        } else {
            int sx = e - 8;
            gt0_r0 = gs[r0 * 16 + 4 + sx];       gt0_r1 = gs[r1 * 16 + 4 + sx];
            gt1_r0 = gs[r0 * 16 + 8 + 4 + sx];   gt1_r1 = gs[r1 * 16 + 8 + 4 + sx];
        }
        #pragma unroll
        for (int c = 0; c < 8; c++) {
            oacc[0][0][c] = fmaf(gt0_r0, o[0][c], oacc[0][0][c]);
            oacc[0][1][c] = fmaf(gt0_r1, o[1][c], oacc[0][1][c]);
            oacc[1][0][c] = fmaf(gt1_r0, o[0][c], oacc[1][0][c]);
            oacc[1][1][c] = fmaf(gt1_r1, o[1][c], oacc[1][1][c]);
        }
    }

    // ---- write out [B, T, 64] ----
    float* outp = out + (size_t)blk * TOKENS * NTASK * HDIM;
    #pragma unroll
    for (int r = 0; r < 2; r++) {
        int row = (r == 0) ? r0 : r1;
        #pragma unroll
        for (int t = 0; t < NTASK; t++) {
            *(float4*)&outp[row * (NTASK * HDIM) + t * HDIM + c0] =
                make_float4(oacc[t][r][0], oacc[t][r][1], oacc[t][r][2], oacc[t][r][3]);
            *(float4*)&outp[row * (NTASK * HDIM) + t * HDIM + c0 + 4] =
                make_float4(oacc[t][r][4], oacc[t][r][5], oacc[t][r][6], oacc[t][r][7]);
        }
    }
}

extern "C" void kernel_launch(void* const* d_in, const int* in_sizes, int n_in,
                              void* d_out, int out_size) {
    const float* X   = (const float*)d_in[0];
    const float* Wt1 = (const float*)d_in[1];
    const float* bt1 = (const float*)d_in[2];
    const float* Wt2 = (const float*)d_in[3];
    const float* bt2 = (const float*)d_in[4];
    const float* Wt3 = (const float*)d_in[5];
    const float* bt3 = (const float*)d_in[6];
    const float* Ws1 = (const float*)d_in[7];
    const float* bs1 = (const float*)d_in[8];
    const float* Ws2 = (const float*)d_in[9];
    const float* bs2 = (const float*)d_in[10];
    const float* Ws3 = (const float*)d_in[11];
    const float* bs3 = (const float*)d_in[12];
    const float* Wg  = (const float*)d_in[13];
    const float* bg  = (const float*)d_in[14];
    float* out = (float*)d_out;

    int B = in_sizes[0] / IN_DIM;         // 65536
    int grid = B / TOKENS;                // 1024

    cudaFuncSetAttribute(mmoe_kernel,
                         cudaFuncAttributeMaxDynamicSharedMemorySize, SMEM_BYTES);

    mmoe_kernel<<<grid, NTHREADS, SMEM_BYTES>>>(
        X, Wt1, bt1, Wt2, bt2, Wt3, bt3,
        Ws1, bs1, Ws2, bs2, Ws3, bs3, Wg, bg, out);
}

// round 5
// speedup vs baseline: 1.7135x; 1.7135x over previous
#include <cuda_runtime.h>
#include <cstdint>

typedef unsigned long long u64;
typedef unsigned int u32;

#define NTHREADS 256
#define TPB      128      // tokens per block
#define IN_DIM   256
#define HDIM     64
#define NEXP     12

#define XSTR 264          // X smem row stride (mult of 4 for f4 align; rowgroup Δ=264 mod 32 = 8 -> conflict-free)
#define HSTR 68           // h smem row stride (Δ=68 mod 32 = 4 -> conflict-free)
#define GSTR 17

#define XS_SZ (TPB*XSTR)          // 33792 floats
#define H_SZ  (TPB*HSTR)          // 8704 floats
#define WB_SZ 4096                // 16KB weight staging (2x8KB double buffer for layer1)
#define GS_SZ (TPB*GSTR)          // 2176 floats
#define SMEM_FLOATS (XS_SZ + 2*H_SZ + WB_SZ + GS_SZ + 64)
#define SMEM_BYTES  (SMEM_FLOATS*4)   // 230,144 B <= 232,448

__device__ __forceinline__ u64 ffma2(u64 a, u64 b, u64 c) {
    u64 d; asm("fma.rn.f32x2 %0,%1,%2,%3;" : "=l"(d) : "l"(a), "l"(b), "l"(c)); return d;
}
__device__ __forceinline__ u64 dup2(float x) {
    u64 d; asm("mov.b64 %0,{%1,%1};" : "=l"(d) : "f"(x)); return d;
}
__device__ __forceinline__ float2 unpack2(u64 v) {
    float2 r; asm("mov.b64 {%0,%1},%2;" : "=f"(r.x), "=f"(r.y) : "l"(v)); return r;
}
__device__ __forceinline__ void lds2u64(u32 a, u64& x, u64& y) {
    asm("ld.shared.v2.u64 {%0,%1},[%2];" : "=l"(x), "=l"(y) : "r"(a));
}
__device__ __forceinline__ u32 sm_addr(const void* p) {
    return (u32)__cvta_generic_to_shared(p);
}
__device__ __forceinline__ void cp16(u32 dst, const void* src) {
    asm volatile("cp.async.cg.shared.global [%0],[%1],16;" :: "r"(dst), "l"(src));
}
#define CP_COMMIT() asm volatile("cp.async.commit_group;" ::: "memory")
#define CP_WAIT0()  asm volatile("cp.async.wait_group 0;" ::: "memory")

// GEMM over KK ks: 4 rows (a0..a3 smem ptrs, k-contiguous) x 8 cols (waddr already
// offset by this thread's col group). acc = 4 rows x 4 col-pairs packed f32x2.
// Per k: 4 scalar a-LDS (broadcast over 8 colgroups, banks distinct via stride),
// 2 LDS.128 for w (full-warp broadcast), 16 FFMA2.
template<int KK>
__device__ __forceinline__ void gemm_run(const float* __restrict__ a0,
                                         const float* __restrict__ a1,
                                         const float* __restrict__ a2,
                                         const float* __restrict__ a3,
                                         u32 waddr, u64 (&acc)[4][4]) {
    #pragma unroll 16
    for (int k = 0; k < KK; k++) {
        u64 A0 = dup2(a0[k]);
        u64 A1 = dup2(a1[k]);
        u64 A2 = dup2(a2[k]);
        u64 A3 = dup2(a3[k]);
        u64 w0, w1, w2, w3;
        lds2u64(waddr + k*256,      w0, w1);
        lds2u64(waddr + k*256 + 16, w2, w3);
        acc[0][0] = ffma2(A0, w0, acc[0][0]); acc[0][1] = ffma2(A0, w1, acc[0][1]);
        acc[0][2] = ffma2(A0, w2, acc[0][2]); acc[0][3] = ffma2(A0, w3, acc[0][3]);
        acc[1][0] = ffma2(A1, w0, acc[1][0]); acc[1][1] = ffma2(A1, w1, acc[1][1]);
        acc[1][2] = ffma2(A1, w2, acc[1][2]); acc[1][3] = ffma2(A1, w3, acc[1][3]);
        acc[2][0] = ffma2(A2, w0, acc[2][0]); acc[2][1] = ffma2(A2, w1, acc[2][1]);
        acc[2][2] = ffma2(A2, w2, acc[2][2]); acc[2][3] = ffma2(A2, w3, acc[2][3]);
        acc[3][0] = ffma2(A3, w0, acc[3][0]); acc[3][1] = ffma2(A3, w1, acc[3][1]);
        acc[3][2] = ffma2(A3, w2, acc[3][2]); acc[3][3] = ffma2(A3, w3, acc[3][3]);
    }
}

__global__ void __launch_bounds__(NTHREADS, 1)
mmoe_kernel(const float* __restrict__ X,
            const float* __restrict__ Wt1, const float* __restrict__ bt1,
            const float* __restrict__ Wt2, const float* __restrict__ bt2,
            const float* __restrict__ Wt3, const float* __restrict__ bt3,
            const float* __restrict__ Ws1, const float* __restrict__ bs1,
            const float* __restrict__ Ws2, const float* __restrict__ bs2,
            const float* __restrict__ Ws3, const float* __restrict__ bs3,
            const float* __restrict__ Wg,  const float* __restrict__ bg,
            float* __restrict__ out)
{
    extern __shared__ float smem[];
    float* Xs  = smem;                 // [128][264]
    float* h1s = Xs + XS_SZ;           // [128][68]
    float* h2s = h1s + H_SZ;           // [128][68]
    float* WbF = h2s + H_SZ;           // 16KB weight staging (also Wg during gates)
    float* gs  = WbF + WB_SZ;          // [128][17] gates
    float* bsm = gs + GS_SZ;           // [64] bias

    const int tid  = threadIdx.x;
    const int blk  = blockIdx.x;
    const int lane = tid & 31;
    const int wrp  = tid >> 5;         // 0..7
    const int rg   = lane >> 3;        // 0..3
    const int cg   = lane & 7;         // 0..7
    const int rbase = wrp * 16 + rg;   // thread rows: rbase + 4*i
    const int c0    = cg * 8;

    const u32 wb_addr = sm_addr(WbF);
    const u32 wb_t    = wb_addr + (u32)(c0 * 4);
    const u32 bs_addr = sm_addr(bsm);

    // ---- load X tile (coalesced float4) ----
    const float* Xblk = X + (size_t)blk * TPB * IN_DIM;
    for (int i = tid; i < TPB * (IN_DIM/4); i += NTHREADS) {
        int row = i >> 6, c4 = i & 63;
        *(float4*)&Xs[row * XSTR + c4 * 4] = ((const float4*)Xblk)[(size_t)row * 64 + c4];
    }
    // ---- stage Wg [2][256][8] into WbF ----
    for (int i = tid; i < (2 * IN_DIM * 8) / 4; i += NTHREADS)
        ((float4*)WbF)[i] = ((const float4*)Wg)[i];
    __syncthreads();

    // ---- gates: thread = (token, task); logits + softmax fused (self-owned) ----
    {
        int tok = tid >> 1, t = tid & 1;
        const float* xr  = Xs + tok * XSTR;
        const float* wgt = WbF + t * (IN_DIM * 8);
        float l[8];
        #pragma unroll
        for (int j = 0; j < 8; j++) l[j] = 0.f;
        #pragma unroll 8
        for (int k = 0; k < IN_DIM; k++) {
            float x = xr[k];
            float4 w0 = *(const float4*)&wgt[k * 8];
            float4 w1 = *(const float4*)&wgt[k * 8 + 4];
            l[0] = fmaf(x, w0.x, l[0]); l[1] = fmaf(x, w0.y, l[1]);
            l[2] = fmaf(x, w0.z, l[2]); l[3] = fmaf(x, w0.w, l[3]);
            l[4] = fmaf(x, w1.x, l[4]); l[5] = fmaf(x, w1.y, l[5]);
            l[6] = fmaf(x, w1.z, l[6]); l[7] = fmaf(x, w1.w, l[7]);
        }
        float m = -1e30f;
        #pragma unroll
        for (int j = 0; j < 8; j++) { l[j] += bg[t * 8 + j]; m = fmaxf(m, l[j]); }
        float s = 0.f;
        #pragma unroll
        for (int j = 0; j < 8; j++) { l[j] = expf(l[j] - m); s += l[j]; }
        float inv = 1.f / s;
        #pragma unroll
        for (int j = 0; j < 8; j++) gs[tok * GSTR + t * 8 + j] = l[j] * inv;
    }
    __syncthreads();   // gates visible; Wg reads done before W1 staging

    u64 oacc[2][4][4];
    #pragma unroll
    for (int t = 0; t < 2; t++)
        #pragma unroll
        for (int i = 0; i < 4; i++)
            #pragma unroll
            for (int j = 0; j < 4; j++) oacc[t][i][j] = 0ull;

    const u64 ONE2 = dup2(1.0f);

    #pragma unroll 1
    for (int e = 0; e < NEXP; e++) {
        const float *W1, *W2, *W3, *b1, *b2, *b3;
        if (e < 8) {
            W1 = Wt1 + e * IN_DIM * HDIM; b1 = bt1 + e * HDIM;
            W2 = Wt2 + e * HDIM * HDIM;   b2 = bt2 + e * HDIM;
            W3 = Wt3 + e * HDIM * HDIM;   b3 = bt3 + e * HDIM;
        } else {
            int s = e - 8;
            W1 = Ws1 + s * IN_DIM * HDIM; b1 = bs1 + s * HDIM;
            W2 = Ws2 + s * HDIM * HDIM;   b2 = bs2 + s * HDIM;
            W3 = Ws3 + s * HDIM * HDIM;   b3 = bs3 + s * HDIM;
        }

        __syncthreads();   // prior readers of WbF done

        // ===== Layer 1: [128x256] @ [256x64], W streamed in 8KB chunks =====
        cp16(wb_addr + tid * 16,        W1 + tid * 4);
        cp16(wb_addr + 4096 + tid * 16, W1 + (tid + 256) * 4);
        if (tid < 16) cp16(bs_addr + tid * 16, b1 + tid * 4);
        CP_COMMIT(); CP_WAIT0();
        __syncthreads();

        u64 acc[4][4] = {};
        #pragma unroll 1
        for (int c = 0; c < 8; c++) {
            if (c < 7) {
                const float* src = W1 + (c + 1) * 2048;
                u32 dst = wb_addr + (u32)(((c + 1) & 1) * 8192);
                cp16(dst + tid * 16,        src + tid * 4);
                cp16(dst + 4096 + tid * 16, src + (tid + 256) * 4);
                CP_COMMIT();
            }
            const float* a0 = Xs + rbase * XSTR + c * 32;
            gemm_run<32>(a0, a0 + 4 * XSTR, a0 + 8 * XSTR, a0 + 12 * XSTR,
                         wb_t + (u32)((c & 1) * 8192), acc);
            CP_WAIT0();
            __syncthreads();
        }
        // h1 = relu(acc + b1)
        #pragma unroll
        for (int i = 0; i < 4; i++) {
            float* hp = h1s + (rbase + 4 * i) * HSTR + c0;
            #pragma unroll
            for (int j = 0; j < 4; j++) {
                float2 v = unpack2(acc[i][j]);
                float2 b = *(const float2*)&bsm[c0 + 2 * j];
                *(float2*)&hp[2 * j] = make_float2(fmaxf(v.x + b.x, 0.f),
                                                   fmaxf(v.y + b.y, 0.f));
            }
        }
        __syncthreads();   // h1 visible; WbF free

        // ===== Layer 2: [128x64] @ [64x64], W2 staged whole (16KB) =====
        #pragma unroll
        for (int j = 0; j < 4; j++)
            cp16(wb_addr + (tid + j * 256) * 16, W2 + (tid + j * 256) * 4);
        if (tid < 16) cp16(bs_addr + tid * 16, b2 + tid * 4);
        CP_COMMIT(); CP_WAIT0();
        __syncthreads();

        u64 acc2[4][4] = {};
        {
            const float* h0 = h1s + rbase * HSTR;
            gemm_run<64>(h0, h0 + 4 * HSTR, h0 + 8 * HSTR, h0 + 12 * HSTR, wb_t, acc2);
        }
        #pragma unroll
        for (int i = 0; i < 4; i++) {
            float* hp = h2s + (rbase + 4 * i) * HSTR + c0;
            #pragma unroll
            for (int j = 0; j < 4; j++) {
                float2 v = unpack2(acc2[i][j]);
                float2 b = *(const float2*)&bsm[c0 + 2 * j];
                *(float2*)&hp[2 * j] = make_float2(fmaxf(v.x + b.x, 0.f),
                                                   fmaxf(v.y + b.y, 0.f));
            }
        }
        __syncthreads();   // h2 visible; WbF free

        // ===== Layer 3: [128x64] @ [64x64] (no relu) =====
        #pragma unroll
        for (int j = 0; j < 4; j++)
            cp16(wb_addr + (tid + j * 256) * 16, W3 + (tid + j * 256) * 4);
        if (tid < 16) cp16(bs_addr + tid * 16, b3 + tid * 4);
        CP_COMMIT(); CP_WAIT0();
        __syncthreads();

        u64 acc3[4][4] = {};
        {
            const float* g0 = h2s + rbase * HSTR;
            gemm_run<64>(g0, g0 + 4 * HSTR, g0 + 8 * HSTR, g0 + 12 * HSTR, wb_t, acc3);
        }

        // ===== gated combine (packed f32x2, static oacc indexing) =====
        float ga[4], gb[4];
        if (e < 8) {
            int t = e >> 2, idx = e & 3;
            #pragma unroll
            for (int i = 0; i < 4; i++) {
                float g = gs[(rbase + 4 * i) * GSTR + t * 8 + idx];
                ga[i] = (t == 0) ? g : 0.f;
                gb[i] = (t == 0) ? 0.f : g;
            }
        } else {
            int sx = e - 8;
            #pragma unroll
            for (int i = 0; i < 4; i++) {
                ga[i] = gs[(rbase + 4 * i) * GSTR + 4 + sx];
                gb[i] = gs[(rbase + 4 * i) * GSTR + 12 + sx];
            }
        }
        #pragma unroll
        for (int i = 0; i < 4; i++) {
            u64 GA = dup2(ga[i]);
            u64 GB = dup2(gb[i]);
            #pragma unroll
            for (int j = 0; j < 4; j++) {
                u64 bp = *(const u64*)&bsm[c0 + 2 * j];
                u64 o  = ffma2(acc3[i][j], ONE2, bp);   // + bias, packed
                oacc[0][i][j] = ffma2(GA, o, oacc[0][i][j]);
                oacc[1][i][j] = ffma2(GB, o, oacc[1][i][j]);
            }
        }
    }

    // ---- write out [B, 2, 64] ----
    float* outp = out + (size_t)blk * TPB * 2 * HDIM;
    #pragma unroll
    for (int t = 0; t < 2; t++) {
        #pragma unroll
        for (int i = 0; i < 4; i++) {
            int row = rbase + 4 * i;
            float2 p0 = unpack2(oacc[t][i][0]);
            float2 p1 = unpack2(oacc[t][i][1]);
            float2 p2 = unpack2(oacc[t][i][2]);
            float2 p3 = unpack2(oacc[t][i][3]);
            *(float4*)&outp[row * 128 + t * 64 + c0]     = make_float4(p0.x, p0.y, p1.x, p1.y);
            *(float4*)&outp[row * 128 + t * 64 + c0 + 4] = make_float4(p2.x, p2.y, p3.x, p3.y);
        }
    }
}

extern "C" void kernel_launch(void* const* d_in, const int* in_sizes, int n_in,
                              void* d_out, int out_size) {
    const float* X   = (const float*)d_in[0];
    const float* Wt1 = (const float*)d_in[1];
    const float* bt1 = (const float*)d_in[2];
    const float* Wt2 = (const float*)d_in[3];
    const float* bt2 = (const float*)d_in[4];
    const float* Wt3 = (const float*)d_in[5];
    const float* bt3 = (const float*)d_in[6];
    const float* Ws1 = (const float*)d_in[7];
    const float* bs1 = (const float*)d_in[8];
    const float* Ws2 = (const float*)d_in[9];
    const float* bs2 = (const float*)d_in[10];
    const float* Ws3 = (const float*)d_in[11];
    const float* bs3 = (const float*)d_in[12];
    const float* Wg  = (const float*)d_in[13];
    const float* bg  = (const float*)d_in[14];
    float* out = (float*)d_out;

    int B = in_sizes[0] / IN_DIM;          // 65536
    int grid = B / TPB;                    // 512

    cudaFuncSetAttribute(mmoe_kernel,
                         cudaFuncAttributeMaxDynamicSharedMemorySize, SMEM_BYTES);

    mmoe_kernel<<<grid, NTHREADS, SMEM_BYTES>>>(
        X, Wt1, bt1, Wt2, bt2, Wt3, bt3,
        Ws1, bs1, Ws2, bs2, Ws3, bs3, Wg, bg, out);
}

// round 7
// speedup vs baseline: 5.0368x; 2.9394x over previous
#include <cuda_runtime.h>
#include <cuda_bf16.h>
#include <cstdint>

typedef unsigned long long u64;
typedef unsigned int u32;

#define NTHREADS 256
#define TPB      128
#define IN_DIM   256
#define HDIM     64
#define NEXP     12

// ---- smem byte offsets ----
#define XH_OFF   0                       // X hi A-frags: [8mt][16kt][32][16B] = 64KB
#define XL_OFF   65536                   // X lo
#define H1H_OFF  131072                  // h1 hi frags: [8mt][4kt][32][16B] = 16KB
#define H1L_OFF  147456
#define H2H_OFF  163840
#define H2L_OFF  180224
#define GS_OFF   196608                  // gates [128][16] fp32 = 8KB
#define SMEM_BYTES 204800

// ---- precomputed B fragments (u64 = {reg0,reg1} per lane) ----
// W1: [e][16kt][8nt][2part][32lane] ; W2/W3: [e][4kt][8nt][2part][32lane]
__device__ u64 g_W1f[NEXP * 16 * 8 * 2 * 32];
__device__ u64 g_W2f[NEXP * 4 * 8 * 2 * 32];
__device__ u64 g_W3f[NEXP * 4 * 8 * 2 * 32];

// ============================ helpers ============================
__device__ __forceinline__ u32 sm_addr(const void* p) {
    return (u32)__cvta_generic_to_shared(p);
}
// pack: lo halfword = first arg, hi halfword = second arg
__device__ __host__ __forceinline__ u32 packbf_h(float v0, float v1) {
#ifdef __CUDA_ARCH__
    u32 r; asm("cvt.rn.bf16x2.f32 %0, %1, %2;" : "=r"(r) : "f"(v1), "f"(v0)); return r;
#else
    return 0;
#endif
}
__device__ __forceinline__ void split_bf(float x, float& h, float& l) {
    h = __bfloat162float(__float2bfloat16_rn(x));
    l = x - h;
}
__device__ __forceinline__ void mma_bf16(float* d, const u32* a, u64 b) {
    u32 b0 = (u32)b, b1 = (u32)(b >> 32);
    asm("mma.sync.aligned.m16n8k16.row.col.f32.bf16.bf16.f32 "
        "{%0,%1,%2,%3},{%4,%5,%6,%7},{%8,%9},{%0,%1,%2,%3};"
        : "+f"(d[0]), "+f"(d[1]), "+f"(d[2]), "+f"(d[3])
        : "r"(a[0]), "r"(a[1]), "r"(a[2]), "r"(a[3]), "r"(b0), "r"(b1));
}
__device__ __forceinline__ void lds128(u32* r, u32 a) {
    asm("ld.shared.v4.b32 {%0,%1,%2,%3},[%4];"
        : "=r"(r[0]), "=r"(r[1]), "=r"(r[2]), "=r"(r[3]) : "r"(a));
}
__device__ __forceinline__ void sts128(u32 a, const u32* r) {
    asm volatile("st.shared.v4.b32 [%0],{%1,%2,%3,%4};"
        :: "r"(a), "r"(r[0]), "r"(r[1]), "r"(r[2]), "r"(r[3]));
}

// ============================ prep kernel ============================
// Writes B fragments in mma.sync layout. For a 16(k)x8(n) B tile:
//   reg0: k = 2*(lane%4)+{0,1}, n = lane/4 ;  reg1: k += 8
__global__ void prep_kernel(const float* __restrict__ Wt1, const float* __restrict__ Wt2,
                            const float* __restrict__ Wt3, const float* __restrict__ Ws1,
                            const float* __restrict__ Ws2, const float* __restrict__ Ws3) {
    int idx = blockIdx.x * blockDim.x + threadIdx.x;
    const float* W; u32* dst; int e, r, KT;
    if (idx < NEXP * 16384) {                       // W1 frags (u32 count)
        e = idx >> 14; r = idx & 16383; KT = 16;
        W = (e < 8) ? Wt1 + e * 16384 : Ws1 + (e - 8) * 16384;
        dst = (u32*)g_W1f + e * 16384;
    } else if (idx < NEXP * 16384 + NEXP * 4096) {  // W2
        int i2 = idx - NEXP * 16384;
        e = i2 >> 12; r = i2 & 4095; KT = 4;
        W = (e < 8) ? Wt2 + e * 4096 : Ws2 + (e - 8) * 4096;
        dst = (u32*)g_W2f + e * 4096;
    } else if (idx < NEXP * 16384 + 2 * NEXP * 4096) { // W3
        int i2 = idx - NEXP * 16384 - NEXP * 4096;
        e = i2 >> 12; r = i2 & 4095; KT = 4;
        W = (e < 8) ? Wt3 + e * 4096 : Ws3 + (e - 8) * 4096;
        dst = (u32*)g_W3f + e * 4096;
    } else return;
    (void)KT;
    int reg  = r & 1;
    int lane = (r >> 1) & 31;
    int part = (r >> 6) & 1;
    int nt   = (r >> 7) & 7;
    int kt   = r >> 10;
    int k0 = kt * 16 + reg * 8 + 2 * (lane & 3);
    int n  = nt * 8 + (lane >> 2);
    float w0 = W[k0 * 64 + n];
    float w1 = W[(k0 + 1) * 64 + n];
    float h0, l0, h1, l1;
    split_bf(w0, h0, l0); split_bf(w1, h1, l1);
    dst[r] = part ? packbf_h(l0, l1) : packbf_h(h0, h1);
}

// ============================ main kernel ============================
__global__ void __launch_bounds__(NTHREADS, 1)
mmoe_mma(const float* __restrict__ X,
         const float* __restrict__ bt1, const float* __restrict__ bt2,
         const float* __restrict__ bt3, const float* __restrict__ bs1,
         const float* __restrict__ bs2, const float* __restrict__ bs3,
         const float* __restrict__ Wg,  const float* __restrict__ bg,
         float* __restrict__ out)
{
    extern __shared__ char sm[];
    float* smf = (float*)sm;
    const int tid  = threadIdx.x;
    const int blk  = blockIdx.x;
    const int lane = tid & 31;
    const int w    = tid >> 5;
    const int wm   = w >> 1;      // 0..3 -> rows wm*32
    const int wn   = w & 1;       // 0..1 -> cols wn*32
    const u32 sb   = sm_addr(sm);

    // ---- stage Wg (16KB) into smem[0..), compute gates ----
    for (int i = tid; i < 4096 / 4; i += NTHREADS)
        ((float4*)smf)[i] = ((const float4*)Wg)[i];
    __syncthreads();
    {
        int tok = tid >> 1, t = tid & 1;
        const float* xr  = X + ((size_t)blk * TPB + tok) * IN_DIM;
        const float* wgt = smf + t * (IN_DIM * 8);
        float lg[8];
        #pragma unroll
        for (int j = 0; j < 8; j++) lg[j] = 0.f;
        #pragma unroll 4
        for (int k = 0; k < IN_DIM; k++) {
            float x = __ldg(xr + k);
            float4 w0 = *(const float4*)&wgt[k * 8];
            float4 w1 = *(const float4*)&wgt[k * 8 + 4];
            lg[0] = fmaf(x, w0.x, lg[0]); lg[1] = fmaf(x, w0.y, lg[1]);
            lg[2] = fmaf(x, w0.z, lg[2]); lg[3] = fmaf(x, w0.w, lg[3]);
            lg[4] = fmaf(x, w1.x, lg[4]); lg[5] = fmaf(x, w1.y, lg[5]);
            lg[6] = fmaf(x, w1.z, lg[6]); lg[7] = fmaf(x, w1.w, lg[7]);
        }
        float m = -1e30f;
        #pragma unroll
        for (int j = 0; j < 8; j++) { lg[j] += __ldg(bg + t * 8 + j); m = fmaxf(m, lg[j]); }
        float s = 0.f;
        #pragma unroll
        for (int j = 0; j < 8; j++) { lg[j] = expf(lg[j] - m); s += lg[j]; }
        float inv = 1.f / s;
        float* gsp = (float*)(sm + GS_OFF) + tok * 16 + t * 8;
        #pragma unroll
        for (int j = 0; j < 8; j++) gsp[j] = lg[j] * inv;
    }
    __syncthreads();

    // ---- convert X -> hi/lo A-fragments in smem ----
    // i -> (mt, kt, lane): thread builds 4 regs (8 X elements)
    {
        const float* Xb = X + (size_t)blk * TPB * IN_DIM;
        for (int i = tid; i < 8 * 16 * 32; i += NTHREADS) {
            int ln = i & 31, kt = (i >> 5) & 15, mt = i >> 9;
            int row = mt * 16 + (ln >> 2);
            int k   = kt * 16 + 2 * (ln & 3);
            float2 e0 = __ldg((const float2*)&Xb[row * IN_DIM + k]);           // reg0
            float2 e1 = __ldg((const float2*)&Xb[(row + 8) * IN_DIM + k]);     // reg1
            float2 e2 = __ldg((const float2*)&Xb[row * IN_DIM + k + 8]);       // reg2
            float2 e3 = __ldg((const float2*)&Xb[(row + 8) * IN_DIM + k + 8]); // reg3
            float h0a,l0a,h0b,l0b, h1a,l1a,h1b,l1b;
            float h2a,l2a,h2b,l2b, h3a,l3a,h3b,l3b;
            split_bf(e0.x,h0a,l0a); split_bf(e0.y,h0b,l0b);
            split_bf(e1.x,h1a,l1a); split_bf(e1.y,h1b,l1b);
            split_bf(e2.x,h2a,l2a); split_bf(e2.y,h2b,l2b);
            split_bf(e3.x,h3a,l3a); split_bf(e3.y,h3b,l3b);
            u32 hi[4] = { packbf_h(h0a,h0b), packbf_h(h1a,h1b),
                          packbf_h(h2a,h2b), packbf_h(h3a,h3b) };
            u32 lo[4] = { packbf_h(l0a,l0b), packbf_h(l1a,l1b),
                          packbf_h(l2a,l2b), packbf_h(l3a,l3b) };
            sts128(sb + XH_OFF + i * 16, hi);
            sts128(sb + XL_OFF + i * 16, lo);
        }
    }
    __syncthreads();

    float oacc[2][2][4][4];
    #pragma unroll
    for (int t = 0; t < 2; t++)
        #pragma unroll
        for (int mt = 0; mt < 2; mt++)
            #pragma unroll
            for (int nt = 0; nt < 4; nt++)
                #pragma unroll
                for (int q = 0; q < 4; q++) oacc[t][mt][nt][q] = 0.f;

    const float* gsr = (const float*)(sm + GS_OFF);

    #pragma unroll 1
    for (int e = 0; e < NEXP; e++) {
        const u64* B1 = g_W1f + e * (16 * 8 * 2 * 32);
        const u64* B2 = g_W2f + e * (4 * 8 * 2 * 32);
        const u64* B3 = g_W3f + e * (4 * 8 * 2 * 32);
        const float* b1 = (e < 8) ? bt1 + e * 64 : bs1 + (e - 8) * 64;
        const float* b2 = (e < 8) ? bt2 + e * 64 : bs2 + (e - 8) * 64;
        const float* b3 = (e < 8) ? bt3 + e * 64 : bs3 + (e - 8) * 64;

        // ================= Layer 1 (K=256, 16 ktiles) =================
        float acc[2][4][4];
        #pragma unroll
        for (int mt = 0; mt < 2; mt++)
            #pragma unroll
            for (int nt = 0; nt < 4; nt++)
                #pragma unroll
                for (int q = 0; q < 4; q++) acc[mt][nt][q] = 0.f;

        #pragma unroll 4
        for (int kt = 0; kt < 16; kt++) {
            u32 ah[2][4], al[2][4];
            #pragma unroll
            for (int mt = 0; mt < 2; mt++) {
                u32 off = (u32)((((wm * 2 + mt) * 16 + kt) * 32 + lane) * 16);
                lds128(ah[mt], sb + XH_OFF + off);
                lds128(al[mt], sb + XL_OFF + off);
            }
            #pragma unroll
            for (int nt = 0; nt < 4; nt++) {
                int bidx = ((kt * 8 + wn * 4 + nt) * 2) * 32 + lane;
                u64 bh = __ldg(B1 + bidx);
                u64 bl = __ldg(B1 + bidx + 32);
                mma_bf16(acc[0][nt], ah[0], bh);
                mma_bf16(acc[1][nt], ah[1], bh);
                mma_bf16(acc[0][nt], al[0], bh);
                mma_bf16(acc[1][nt], al[1], bh);
                mma_bf16(acc[0][nt], ah[0], bl);
                mma_bf16(acc[1][nt], ah[1], bl);
            }
        }
        // epilogue -> h1 frags (bias, relu, split, STS.128)
        #pragma unroll
        for (int mt = 0; mt < 2; mt++) {
            #pragma unroll
            for (int p = 0; p < 2; p++) {
                u32 hi[4], lo[4];
                #pragma unroll
                for (int q = 0; q < 2; q++) {
                    int nt = p * 2 + q;
                    int col = wn * 32 + nt * 8 + 2 * (lane & 3);
                    float2 bb = __ldg((const float2*)&b1[col]);
                    float v0 = fmaxf(acc[mt][nt][0] + bb.x, 0.f);
                    float v1 = fmaxf(acc[mt][nt][1] + bb.y, 0.f);
                    float v2 = fmaxf(acc[mt][nt][2] + bb.x, 0.f);
                    float v3 = fmaxf(acc[mt][nt][3] + bb.y, 0.f);
                    float h0,l0,h1,l1,h2,l2,h3,l3;
                    split_bf(v0,h0,l0); split_bf(v1,h1,l1);
                    split_bf(v2,h2,l2); split_bf(v3,h3,l3);
                    hi[q * 2]     = packbf_h(h0, h1);
                    hi[q * 2 + 1] = packbf_h(h2, h3);
                    lo[q * 2]     = packbf_h(l0, l1);
                    lo[q * 2 + 1] = packbf_h(l2, l3);
                }
                u32 off = (u32)((((wm * 2 + mt) * 4 + wn * 2 + p) * 32 + lane) * 16);
                sts128(sb + H1H_OFF + off, hi);
                sts128(sb + H1L_OFF + off, lo);
            }
        }
        __syncthreads();

        // ================= Layer 2 (K=64, 4 ktiles) =================
        #pragma unroll
        for (int mt = 0; mt < 2; mt++)
            #pragma unroll
            for (int nt = 0; nt < 4; nt++)
                #pragma unroll
                for (int q = 0; q < 4; q++) acc[mt][nt][q] = 0.f;
        #pragma unroll
        for (int kt = 0; kt < 4; kt++) {
            u32 ah[2][4], al[2][4];
            #pragma unroll
            for (int mt = 0; mt < 2; mt++) {
                u32 off = (u32)((((wm * 2 + mt) * 4 + kt) * 32 + lane) * 16);
                lds128(ah[mt], sb + H1H_OFF + off);
                lds128(al[mt], sb + H1L_OFF + off);
            }
            #pragma unroll
            for (int nt = 0; nt < 4; nt++) {
                int bidx = ((kt * 8 + wn * 4 + nt) * 2) * 32 + lane;
                u64 bh = __ldg(B2 + bidx);
                u64 bl = __ldg(B2 + bidx + 32);
                mma_bf16(acc[0][nt], ah[0], bh);
                mma_bf16(acc[1][nt], ah[1], bh);
                mma_bf16(acc[0][nt], al[0], bh);
                mma_bf16(acc[1][nt], al[1], bh);
                mma_bf16(acc[0][nt], ah[0], bl);
                mma_bf16(acc[1][nt], ah[1], bl);
            }
        }
        #pragma unroll
        for (int mt = 0; mt < 2; mt++) {
            #pragma unroll
            for (int p = 0; p < 2; p++) {
                u32 hi[4], lo[4];
                #pragma unroll
                for (int q = 0; q < 2; q++) {
                    int nt = p * 2 + q;
                    int col = wn * 32 + nt * 8 + 2 * (lane & 3);
                    float2 bb = __ldg((const float2*)&b2[col]);
                    float v0 = fmaxf(acc[mt][nt][0] + bb.x, 0.f);
                    float v1 = fmaxf(acc[mt][nt][1] + bb.y, 0.f);
                    float v2 = fmaxf(acc[mt][nt][2] + bb.x, 0.f);
                    float v3 = fmaxf(acc[mt][nt][3] + bb.y, 0.f);
                    float h0,l0,h1,l1,h2,l2,h3,l3;
                    split_bf(v0,h0,l0); split_bf(v1,h1,l1);
                    split_bf(v2,h2,l2); split_bf(v3,h3,l3);
                    hi[q * 2]     = packbf_h(h0, h1);
                    hi[q * 2 + 1] = packbf_h(h2, h3);
                    lo[q * 2]     = packbf_h(l0, l1);
                    lo[q * 2 + 1] = packbf_h(l2, l3);
                }
                u32 off = (u32)((((wm * 2 + mt) * 4 + wn * 2 + p) * 32 + lane) * 16);
                sts128(sb + H2H_OFF + off, hi);
                sts128(sb + H2L_OFF + off, lo);
            }
        }
        __syncthreads();

        // ================= Layer 3 (K=64) + gated combine =================
        #pragma unroll
        for (int mt = 0; mt < 2; mt++)
            #pragma unroll
            for (int nt = 0; nt < 4; nt++)
                #pragma unroll
                for (int q = 0; q < 4; q++) acc[mt][nt][q] = 0.f;
        #pragma unroll
        for (int kt = 0; kt < 4; kt++) {
            u32 ah[2][4], al[2][4];
            #pragma unroll
            for (int mt = 0; mt < 2; mt++) {
                u32 off = (u32)((((wm * 2 + mt) * 4 + kt) * 32 + lane) * 16);
                lds128(ah[mt], sb + H2H_OFF + off);
                lds128(al[mt], sb + H2L_OFF + off);
            }
            #pragma unroll
            for (int nt = 0; nt < 4; nt++) {
                int bidx = ((kt * 8 + wn * 4 + nt) * 2) * 32 + lane;
                u64 bh = __ldg(B3 + bidx);
                u64 bl = __ldg(B3 + bidx + 32);
                mma_bf16(acc[0][nt], ah[0], bh);
                mma_bf16(acc[1][nt], ah[1], bh);
                mma_bf16(acc[0][nt], al[0], bh);
                mma_bf16(acc[1][nt], al[1], bh);
                mma_bf16(acc[0][nt], ah[0], bl);
                mma_bf16(acc[1][nt], ah[1], bl);
            }
        }
        // gates for this expert, 4 rows per thread (2 mt x {r, r+8})
        float g0r[2][2], g1r[2][2];
        #pragma unroll
        for (int mt = 0; mt < 2; mt++) {
            #pragma unroll
            for (int rh = 0; rh < 2; rh++) {
                int row = wm * 32 + mt * 16 + (lane >> 2) + rh * 8;
                float a, b;
                if (e < 8) {
                    int t = e >> 2, ix = e & 3;
                    float g = gsr[row * 16 + t * 8 + ix];
                    a = t ? 0.f : g;
                    b = t ? g : 0.f;
                } else {
                    int sx = e - 8;
                    a = gsr[row * 16 + 4 + sx];
                    b = gsr[row * 16 + 12 + sx];
                }
                g0r[mt][rh] = a; g1r[mt][rh] = b;
            }
        }
        #pragma unroll
        for (int mt = 0; mt < 2; mt++) {
            #pragma unroll
            for (int nt = 0; nt < 4; nt++) {
                int col = wn * 32 + nt * 8 + 2 * (lane & 3);
                float2 bb = __ldg((const float2*)&b3[col]);
                float v0 = acc[mt][nt][0] + bb.x;
                float v1 = acc[mt][nt][1] + bb.y;
                float v2 = acc[mt][nt][2] + bb.x;
                float v3 = acc[mt][nt][3] + bb.y;
                oacc[0][mt][nt][0] = fmaf(g0r[mt][0], v0, oacc[0][mt][nt][0]);
                oacc[0][mt][nt][1] = fmaf(g0r[mt][0], v1, oacc[0][mt][nt][1]);
                oacc[0][mt][nt][2] = fmaf(g0r[mt][1], v2, oacc[0][mt][nt][2]);
                oacc[0][mt][nt][3] = fmaf(g0r[mt][1], v3, oacc[0][mt][nt][3]);
                oacc[1][mt][nt][0] = fmaf(g1r[mt][0], v0, oacc[1][mt][nt][0]);
                oacc[1][mt][nt][1] = fmaf(g1r[mt][0], v1, oacc[1][mt][nt][1]);
                oacc[1][mt][nt][2] = fmaf(g1r[mt][1], v2, oacc[1][mt][nt][2]);
                oacc[1][mt][nt][3] = fmaf(g1r[mt][1], v3, oacc[1][mt][nt][3]);
            }
        }
        __syncthreads();
    }

    // ---- write output [B, 2, 64] ----
    float* ob = out + (size_t)blk * TPB * 128;
    #pragma unroll
    for (int t = 0; t < 2; t++) {
        #pragma unroll
        for (int mt = 0; mt < 2; mt++) {
            #pragma unroll
            for (int rh = 0; rh < 2; rh++) {
                int row = wm * 32 + mt * 16 + (lane >> 2) + rh * 8;
                #pragma unroll
                for (int nt = 0; nt < 4; nt++) {
                    int col = wn * 32 + nt * 8 + 2 * (lane & 3);
                    float2 v = make_float2(oacc[t][mt][nt][rh * 2],
                                           oacc[t][mt][nt][rh * 2 + 1]);
                    *(float2*)&ob[row * 128 + t * 64 + col] = v;
                }
            }
        }
    }
}

// ============================ launch ============================
extern "C" void kernel_launch(void* const* d_in, const int* in_sizes, int n_in,
                              void* d_out, int out_size) {
    const float* X   = (const float*)d_in[0];
    const float* Wt1 = (const float*)d_in[1];
    const float* bt1 = (const float*)d_in[2];
    const float* Wt2 = (const float*)d_in[3];
    const float* bt2 = (const float*)d_in[4];
    const float* Wt3 = (const float*)d_in[5];
    const float* bt3 = (const float*)d_in[6];
    const float* Ws1 = (const float*)d_in[7];
    const float* bs1 = (const float*)d_in[8];
    const float* Ws2 = (const float*)d_in[9];
    const float* bs2 = (const float*)d_in[10];
    const float* Ws3 = (const float*)d_in[11];
    const float* bs3 = (const float*)d_in[12];
    const float* Wg  = (const float*)d_in[13];
    const float* bg  = (const float*)d_in[14];
    float* out = (float*)d_out;

    int B = in_sizes[0] / IN_DIM;          // 65536
    int grid = B / TPB;                    // 512

    int prep_total = NEXP * 16384 + 2 * NEXP * 4096;   // 294912
    prep_kernel<<<(prep_total + 255) / 256, 256>>>(Wt1, Wt2, Wt3, Ws1, Ws2, Ws3);

    cudaFuncSetAttribute(mmoe_mma, cudaFuncAttributeMaxDynamicSharedMemorySize, SMEM_BYTES);
    mmoe_mma<<<grid, NTHREADS, SMEM_BYTES>>>(
        X, bt1, bt2, bt3, bs1, bs2, bs3, Wg, bg, out);
}

// round 8
// speedup vs baseline: 5.4945x; 1.0909x over previous
#include <cuda_runtime.h>
#include <cuda_bf16.h>
#include <cstdint>

typedef unsigned long long u64;
typedef unsigned int u32;

#define NTHREADS 512
#define TPB      128
#define IN_DIM   256
#define HDIM     64
#define NEXP     12

// ---- smem byte offsets ----
#define XH_OFF   0                       // X hi A-frags: [8mt][16kt][32][16B] = 64KB
#define XL_OFF   65536                   // X lo
#define H1H_OFF  131072                  // h1 hi frags: [8mt][4kt][32][16B] = 16KB
#define H1L_OFF  147456
#define H2H_OFF  163840
#define H2L_OFF  180224
#define GS_OFF   196608                  // gates [128][17] fp32
#define SMEM_BYTES (196608 + 128*17*4)   // 205312

// ---- precomputed B fragments (u64 = {reg0,reg1} per lane) ----
// W1: [e][16kt][8nt][2part][32lane] ; W2/W3: [e][4kt][8nt][2part][32lane]
__device__ u64 g_W1f[NEXP * 16 * 8 * 2 * 32];
__device__ u64 g_W2f[NEXP * 4 * 8 * 2 * 32];
__device__ u64 g_W3f[NEXP * 4 * 8 * 2 * 32];

// ============================ helpers ============================
__device__ __forceinline__ u32 sm_addr(const void* p) {
    return (u32)__cvta_generic_to_shared(p);
}
__device__ __host__ __forceinline__ u32 packbf_h(float v0, float v1) {
#ifdef __CUDA_ARCH__
    u32 r; asm("cvt.rn.bf16x2.f32 %0, %1, %2;" : "=r"(r) : "f"(v1), "f"(v0)); return r;
#else
    return 0;
#endif
}
__device__ __forceinline__ void split_bf(float x, float& h, float& l) {
    h = __bfloat162float(__float2bfloat16_rn(x));
    l = x - h;
}
__device__ __forceinline__ void mma_bf16(float* d, const u32* a, u64 b) {
    u32 b0 = (u32)b, b1 = (u32)(b >> 32);
    asm("mma.sync.aligned.m16n8k16.row.col.f32.bf16.bf16.f32 "
        "{%0,%1,%2,%3},{%4,%5,%6,%7},{%8,%9},{%0,%1,%2,%3};"
        : "+f"(d[0]), "+f"(d[1]), "+f"(d[2]), "+f"(d[3])
        : "r"(a[0]), "r"(a[1]), "r"(a[2]), "r"(a[3]), "r"(b0), "r"(b1));
}
__device__ __forceinline__ void lds128(u32* r, u32 a) {
    asm("ld.shared.v4.b32 {%0,%1,%2,%3},[%4];"
        : "=r"(r[0]), "=r"(r[1]), "=r"(r[2]), "=r"(r[3]) : "r"(a));
}
__device__ __forceinline__ void sts128(u32 a, const u32* r) {
    asm volatile("st.shared.v4.b32 [%0],{%1,%2,%3,%4};"
        :: "r"(a), "r"(r[0]), "r"(r[1]), "r"(r[2]), "r"(r[3]));
}

// ============================ prep kernel ============================
__global__ void prep_kernel(const float* __restrict__ Wt1, const float* __restrict__ Wt2,
                            const float* __restrict__ Wt3, const float* __restrict__ Ws1,
                            const float* __restrict__ Ws2, const float* __restrict__ Ws3) {
    int idx = blockIdx.x * blockDim.x + threadIdx.x;
    const float* W; u32* dst; int e, r;
    if (idx < NEXP * 16384) {
        e = idx >> 14; r = idx & 16383;
        W = (e < 8) ? Wt1 + e * 16384 : Ws1 + (e - 8) * 16384;
        dst = (u32*)g_W1f + e * 16384;
    } else if (idx < NEXP * 16384 + NEXP * 4096) {
        int i2 = idx - NEXP * 16384;
        e = i2 >> 12; r = i2 & 4095;
        W = (e < 8) ? Wt2 + e * 4096 : Ws2 + (e - 8) * 4096;
        dst = (u32*)g_W2f + e * 4096;
    } else if (idx < NEXP * 16384 + 2 * NEXP * 4096) {
        int i2 = idx - NEXP * 16384 - NEXP * 4096;
        e = i2 >> 12; r = i2 & 4095;
        W = (e < 8) ? Wt3 + e * 4096 : Ws3 + (e - 8) * 4096;
        dst = (u32*)g_W3f + e * 4096;
    } else return;
    int reg  = r & 1;
    int lane = (r >> 1) & 31;
    int part = (r >> 6) & 1;
    int nt   = (r >> 7) & 7;
    int kt   = r >> 10;
    int k0 = kt * 16 + reg * 8 + 2 * (lane & 3);
    int n  = nt * 8 + (lane >> 2);
    float w0 = W[k0 * 64 + n];
    float w1 = W[(k0 + 1) * 64 + n];
    float h0, l0, h1, l1;
    split_bf(w0, h0, l0); split_bf(w1, h1, l1);
    dst[r] = part ? packbf_h(l0, l1) : packbf_h(h0, h1);
}

// ============================ main kernel ============================
__global__ void __launch_bounds__(NTHREADS, 1)
mmoe_mma(const float* __restrict__ X,
         const float* __restrict__ bt1, const float* __restrict__ bt2,
         const float* __restrict__ bt3, const float* __restrict__ bs1,
         const float* __restrict__ bs2, const float* __restrict__ bs3,
         const float* __restrict__ Wg,  const float* __restrict__ bg,
         float* __restrict__ out)
{
    extern __shared__ char sm[];
    float* smf = (float*)sm;
    const int tid  = threadIdx.x;
    const int blk  = blockIdx.x;
    const int lane = tid & 31;
    const int w    = tid >> 5;
    const int wm   = w >> 2;      // 0..3 -> rows wm*32
    const int wn   = w & 3;       // 0..3 -> cols wn*16
    const u32 sb   = sm_addr(sm);

    // ---- stage Wg (16KB), compute gates (threads 0..255) ----
    for (int i = tid; i < 4096 / 4; i += NTHREADS)
        ((float4*)smf)[i] = ((const float4*)Wg)[i];
    __syncthreads();
    if (tid < 256) {
        int tok = tid >> 1, t = tid & 1;
        const float* xr  = X + ((size_t)blk * TPB + tok) * IN_DIM;
        const float* wgt = smf + t * (IN_DIM * 8);
        float lg[8];
        #pragma unroll
        for (int j = 0; j < 8; j++) lg[j] = 0.f;
        #pragma unroll 4
        for (int k = 0; k < IN_DIM; k++) {
            float x = __ldg(xr + k);
            float4 w0 = *(const float4*)&wgt[k * 8];
            float4 w1 = *(const float4*)&wgt[k * 8 + 4];
            lg[0] = fmaf(x, w0.x, lg[0]); lg[1] = fmaf(x, w0.y, lg[1]);
            lg[2] = fmaf(x, w0.z, lg[2]); lg[3] = fmaf(x, w0.w, lg[3]);
            lg[4] = fmaf(x, w1.x, lg[4]); lg[5] = fmaf(x, w1.y, lg[5]);
            lg[6] = fmaf(x, w1.z, lg[6]); lg[7] = fmaf(x, w1.w, lg[7]);
        }
        float m = -1e30f;
        #pragma unroll
        for (int j = 0; j < 8; j++) { lg[j] += __ldg(bg + t * 8 + j); m = fmaxf(m, lg[j]); }
        float s = 0.f;
        #pragma unroll
        for (int j = 0; j < 8; j++) { lg[j] = expf(lg[j] - m); s += lg[j]; }
        float inv = 1.f / s;
        float* gsp = (float*)(sm + GS_OFF) + tok * 17 + t * 8;
        #pragma unroll
        for (int j = 0; j < 8; j++) gsp[j] = lg[j] * inv;
    }
    __syncthreads();

    // ---- convert X -> hi/lo A-fragments in smem ----
    {
        const float* Xb = X + (size_t)blk * TPB * IN_DIM;
        for (int i = tid; i < 8 * 16 * 32; i += NTHREADS) {
            int ln = i & 31, kt = (i >> 5) & 15, mt = i >> 9;
            int row = mt * 16 + (ln >> 2);
            int k   = kt * 16 + 2 * (ln & 3);
            float2 e0 = __ldg((const float2*)&Xb[row * IN_DIM + k]);
            float2 e1 = __ldg((const float2*)&Xb[(row + 8) * IN_DIM + k]);
            float2 e2 = __ldg((const float2*)&Xb[row * IN_DIM + k + 8]);
            float2 e3 = __ldg((const float2*)&Xb[(row + 8) * IN_DIM + k + 8]);
            float h0a,l0a,h0b,l0b, h1a,l1a,h1b,l1b;
            float h2a,l2a,h2b,l2b, h3a,l3a,h3b,l3b;
            split_bf(e0.x,h0a,l0a); split_bf(e0.y,h0b,l0b);
            split_bf(e1.x,h1a,l1a); split_bf(e1.y,h1b,l1b);
            split_bf(e2.x,h2a,l2a); split_bf(e2.y,h2b,l2b);
            split_bf(e3.x,h3a,l3a); split_bf(e3.y,h3b,l3b);
            u32 hi[4] = { packbf_h(h0a,h0b), packbf_h(h1a,h1b),
                          packbf_h(h2a,h2b), packbf_h(h3a,h3b) };
            u32 lo[4] = { packbf_h(l0a,l0b), packbf_h(l1a,l1b),
                          packbf_h(l2a,l2b), packbf_h(l3a,l3b) };
            sts128(sb + XH_OFF + i * 16, hi);
            sts128(sb + XL_OFF + i * 16, lo);
        }
    }
    __syncthreads();

    float oacc[2][2][2][4];     // [task][mt][nt][reg]
    #pragma unroll
    for (int t = 0; t < 2; t++)
        #pragma unroll
        for (int mt = 0; mt < 2; mt++)
            #pragma unroll
            for (int nt = 0; nt < 2; nt++)
                #pragma unroll
                for (int q = 0; q < 4; q++) oacc[t][mt][nt][q] = 0.f;

    const float* gsr = (const float*)(sm + GS_OFF);

    #pragma unroll 1
    for (int e = 0; e < NEXP; e++) {
        const u64* B1 = g_W1f + e * (16 * 8 * 2 * 32);
        const u64* B2 = g_W2f + e * (4 * 8 * 2 * 32);
        const u64* B3 = g_W3f + e * (4 * 8 * 2 * 32);
        const float* b1 = (e < 8) ? bt1 + e * 64 : bs1 + (e - 8) * 64;
        const float* b2 = (e < 8) ? bt2 + e * 64 : bs2 + (e - 8) * 64;
        const float* b3 = (e < 8) ? bt3 + e * 64 : bs3 + (e - 8) * 64;

        float acc[2][2][4];     // [mt][nt][reg]

        // ================= Layer 1 (K=256, 16 ktiles) =================
        #pragma unroll
        for (int mt = 0; mt < 2; mt++)
            #pragma unroll
            for (int nt = 0; nt < 2; nt++)
                #pragma unroll
                for (int q = 0; q < 4; q++) acc[mt][nt][q] = 0.f;

        #pragma unroll 2
        for (int kt = 0; kt < 16; kt++) {
            u32 ah[2][4], al[2][4];
            #pragma unroll
            for (int mt = 0; mt < 2; mt++) {
                u32 off = (u32)((((wm * 2 + mt) * 16 + kt) * 32 + lane) * 16);
                lds128(ah[mt], sb + XH_OFF + off);
                lds128(al[mt], sb + XL_OFF + off);
            }
            u64 bh[2], bl[2];
            #pragma unroll
            for (int nt = 0; nt < 2; nt++) {
                int bidx = ((kt * 8 + wn * 2 + nt) * 2) * 32 + lane;
                bh[nt] = __ldg(B1 + bidx);
                bl[nt] = __ldg(B1 + bidx + 32);
            }
            #pragma unroll
            for (int nt = 0; nt < 2; nt++) {
                mma_bf16(acc[0][nt], ah[0], bh[nt]);
                mma_bf16(acc[1][nt], ah[1], bh[nt]);
            }
            #pragma unroll
            for (int nt = 0; nt < 2; nt++) {
                mma_bf16(acc[0][nt], al[0], bh[nt]);
                mma_bf16(acc[1][nt], al[1], bh[nt]);
            }
            #pragma unroll
            for (int nt = 0; nt < 2; nt++) {
                mma_bf16(acc[0][nt], ah[0], bl[nt]);
                mma_bf16(acc[1][nt], ah[1], bl[nt]);
            }
        }
        // epilogue -> h1 frags
        #pragma unroll
        for (int mt = 0; mt < 2; mt++) {
            u32 hi[4], lo[4];
            #pragma unroll
            for (int nt = 0; nt < 2; nt++) {
                int col = wn * 16 + nt * 8 + 2 * (lane & 3);
                float2 bb = __ldg((const float2*)&b1[col]);
                float v0 = fmaxf(acc[mt][nt][0] + bb.x, 0.f);
                float v1 = fmaxf(acc[mt][nt][1] + bb.y, 0.f);
                float v2 = fmaxf(acc[mt][nt][2] + bb.x, 0.f);
                float v3 = fmaxf(acc[mt][nt][3] + bb.y, 0.f);
                float h0,l0,h1,l1,h2,l2,h3,l3;
                split_bf(v0,h0,l0); split_bf(v1,h1,l1);
                split_bf(v2,h2,l2); split_bf(v3,h3,l3);
                hi[nt * 2]     = packbf_h(h0, h1);
                hi[nt * 2 + 1] = packbf_h(h2, h3);
                lo[nt * 2]     = packbf_h(l0, l1);
                lo[nt * 2 + 1] = packbf_h(l2, l3);
            }
            u32 off = (u32)((((wm * 2 + mt) * 4 + wn) * 32 + lane) * 16);
            sts128(sb + H1H_OFF + off, hi);
            sts128(sb + H1L_OFF + off, lo);
        }
        __syncthreads();

        // ================= Layer 2 (K=64, 4 ktiles) =================
        #pragma unroll
        for (int mt = 0; mt < 2; mt++)
            #pragma unroll
            for (int nt = 0; nt < 2; nt++)
                #pragma unroll
                for (int q = 0; q < 4; q++) acc[mt][nt][q] = 0.f;
        #pragma unroll
        for (int kt = 0; kt < 4; kt++) {
            u32 ah[2][4], al[2][4];
            #pragma unroll
            for (int mt = 0; mt < 2; mt++) {
                u32 off = (u32)((((wm * 2 + mt) * 4 + kt) * 32 + lane) * 16);
                lds128(ah[mt], sb + H1H_OFF + off);
                lds128(al[mt], sb + H1L_OFF + off);
            }
            u64 bh[2], bl[2];
            #pragma unroll
            for (int nt = 0; nt < 2; nt++) {
                int bidx = ((kt * 8 + wn * 2 + nt) * 2) * 32 + lane;
                bh[nt] = __ldg(B2 + bidx);
                bl[nt] = __ldg(B2 + bidx + 32);
            }
            #pragma unroll
            for (int nt = 0; nt < 2; nt++) {
                mma_bf16(acc[0][nt], ah[0], bh[nt]);
                mma_bf16(acc[1][nt], ah[1], bh[nt]);
            }
            #pragma unroll
            for (int nt = 0; nt < 2; nt++) {
                mma_bf16(acc[0][nt], al[0], bh[nt]);
                mma_bf16(acc[1][nt], al[1], bh[nt]);
            }
            #pragma unroll
            for (int nt = 0; nt < 2; nt++) {
                mma_bf16(acc[0][nt], ah[0], bl[nt]);
                mma_bf16(acc[1][nt], ah[1], bl[nt]);
            }
        }
        #pragma unroll
        for (int mt = 0; mt < 2; mt++) {
            u32 hi[4], lo[4];
            #pragma unroll
            for (int nt = 0; nt < 2; nt++) {
                int col = wn * 16 + nt * 8 + 2 * (lane & 3);
                float2 bb = __ldg((const float2*)&b2[col]);
                float v0 = fmaxf(acc[mt][nt][0] + bb.x, 0.f);
                float v1 = fmaxf(acc[mt][nt][1] + bb.y, 0.f);
                float v2 = fmaxf(acc[mt][nt][2] + bb.x, 0.f);
                float v3 = fmaxf(acc[mt][nt][3] + bb.y, 0.f);
                float h0,l0,h1,l1,h2,l2,h3,l3;
                split_bf(v0,h0,l0); split_bf(v1,h1,l1);
                split_bf(v2,h2,l2); split_bf(v3,h3,l3);
                hi[nt * 2]     = packbf_h(h0, h1);
                hi[nt * 2 + 1] = packbf_h(h2, h3);
                lo[nt * 2]     = packbf_h(l0, l1);
                lo[nt * 2 + 1] = packbf_h(l2, l3);
            }
            u32 off = (u32)((((wm * 2 + mt) * 4 + wn) * 32 + lane) * 16);
            sts128(sb + H2H_OFF + off, hi);
            sts128(sb + H2L_OFF + off, lo);
        }
        __syncthreads();

        // ================= Layer 3 (K=64) + gated combine =================
        #pragma unroll
        for (int mt = 0; mt < 2; mt++)
            #pragma unroll
            for (int nt = 0; nt < 2; nt++)
                #pragma unroll
                for (int q = 0; q < 4; q++) acc[mt][nt][q] = 0.f;
        #pragma unroll
        for (int kt = 0; kt < 4; kt++) {
            u32 ah[2][4], al[2][4];
            #pragma unroll
            for (int mt = 0; mt < 2; mt++) {
                u32 off = (u32)((((wm * 2 + mt) * 4 + kt) * 32 + lane) * 16);
                lds128(ah[mt], sb + H2H_OFF + off);
                lds128(al[mt], sb + H2L_OFF + off);
            }
            u64 bh[2], bl[2];
            #pragma unroll
            for (int nt = 0; nt < 2; nt++) {
                int bidx = ((kt * 8 + wn * 2 + nt) * 2) * 32 + lane;
                bh[nt] = __ldg(B3 + bidx);
                bl[nt] = __ldg(B3 + bidx + 32);
            }
            #pragma unroll
            for (int nt = 0; nt < 2; nt++) {
                mma_bf16(acc[0][nt], ah[0], bh[nt]);
                mma_bf16(acc[1][nt], ah[1], bh[nt]);
            }
            #pragma unroll
            for (int nt = 0; nt < 2; nt++) {
                mma_bf16(acc[0][nt], al[0], bh[nt]);
                mma_bf16(acc[1][nt], al[1], bh[nt]);
            }
            #pragma unroll
            for (int nt = 0; nt < 2; nt++) {
                mma_bf16(acc[0][nt], ah[0], bl[nt]);
                mma_bf16(acc[1][nt], ah[1], bl[nt]);
            }
        }
        // gates: 4 rows per thread (2 mt x {r, r+8})
        float g0r[2][2], g1r[2][2];
        #pragma unroll
        for (int mt = 0; mt < 2; mt++) {
            #pragma unroll
            for (int rh = 0; rh < 2; rh++) {
                int row = wm * 32 + mt * 16 + (lane >> 2) + rh * 8;
                float a, b;
                if (e < 8) {
                    int t = e >> 2, ix = e & 3;
                    float g = gsr[row * 17 + t * 8 + ix];
                    a = t ? 0.f : g;
                    b = t ? g : 0.f;
                } else {
                    int sx = e - 8;
                    a = gsr[row * 17 + 4 + sx];
                    b = gsr[row * 17 + 12 + sx];
                }
                g0r[mt][rh] = a; g1r[mt][rh] = b;
            }
        }
        #pragma unroll
        for (int mt = 0; mt < 2; mt++) {
            #pragma unroll
            for (int nt = 0; nt < 2; nt++) {
                int col = wn * 16 + nt * 8 + 2 * (lane & 3);
                float2 bb = __ldg((const float2*)&b3[col]);
                float v0 = acc[mt][nt][0] + bb.x;
                float v1 = acc[mt][nt][1] + bb.y;
                float v2 = acc[mt][nt][2] + bb.x;
                float v3 = acc[mt][nt][3] + bb.y;
                oacc[0][mt][nt][0] = fmaf(g0r[mt][0], v0, oacc[0][mt][nt][0]);
                oacc[0][mt][nt][1] = fmaf(g0r[mt][0], v1, oacc[0][mt][nt][1]);
                oacc[0][mt][nt][2] = fmaf(g0r[mt][1], v2, oacc[0][mt][nt][2]);
                oacc[0][mt][nt][3] = fmaf(g0r[mt][1], v3, oacc[0][mt][nt][3]);
                oacc[1][mt][nt][0] = fmaf(g1r[mt][0], v0, oacc[1][mt][nt][0]);
                oacc[1][mt][nt][1] = fmaf(g1r[mt][0], v1, oacc[1][mt][nt][1]);
                oacc[1][mt][nt][2] = fmaf(g1r[mt][1], v2, oacc[1][mt][nt][2]);
                oacc[1][mt][nt][3] = fmaf(g1r[mt][1], v3, oacc[1][mt][nt][3]);
            }
        }
        __syncthreads();
    }

    // ---- write output [B, 2, 64] ----
    float* ob = out + (size_t)blk * TPB * 128;
    #pragma unroll
    for (int t = 0; t < 2; t++) {
        #pragma unroll
        for (int mt = 0; mt < 2; mt++) {
            #pragma unroll
            for (int rh = 0; rh < 2; rh++) {
                int row = wm * 32 + mt * 16 + (lane >> 2) + rh * 8;
                #pragma unroll
                for (int nt = 0; nt < 2; nt++) {
                    int col = wn * 16 + nt * 8 + 2 * (lane & 3);
                    float2 v = make_float2(oacc[t][mt][nt][rh * 2],
                                           oacc[t][mt][nt][rh * 2 + 1]);
                    *(float2*)&ob[row * 128 + t * 64 + col] = v;
                }
            }
        }
    }
}

// ============================ launch ============================
extern "C" void kernel_launch(void* const* d_in, const int* in_sizes, int n_in,
                              void* d_out, int out_size) {
    const float* X   = (const float*)d_in[0];
    const float* Wt1 = (const float*)d_in[1];
    const float* bt1 = (const float*)d_in[2];
    const float* Wt2 = (const float*)d_in[3];
    const float* bt2 = (const float*)d_in[4];
    const float* Wt3 = (const float*)d_in[5];
    const float* bt3 = (const float*)d_in[6];
    const float* Ws1 = (const float*)d_in[7];
    const float* bs1 = (const float*)d_in[8];
    const float* Ws2 = (const float*)d_in[9];
    const float* bs2 = (const float*)d_in[10];
    const float* Ws3 = (const float*)d_in[11];
    const float* bs3 = (const float*)d_in[12];
    const float* Wg  = (const float*)d_in[13];
    const float* bg  = (const float*)d_in[14];
    float* out = (float*)d_out;

    int B = in_sizes[0] / IN_DIM;          // 65536
    int grid = B / TPB;                    // 512

    int prep_total = NEXP * 16384 + 2 * NEXP * 4096;   // 294912
    prep_kernel<<<(prep_total + 255) / 256, 256>>>(Wt1, Wt2, Wt3, Ws1, Ws2, Ws3);

    cudaFuncSetAttribute(mmoe_mma, cudaFuncAttributeMaxDynamicSharedMemorySize, SMEM_BYTES);
    mmoe_mma<<<grid, NTHREADS, SMEM_BYTES>>>(
        X, bt1, bt2, bt3, bs1, bs2, bs3, Wg, bg, out);
}

// round 9
// speedup vs baseline: 6.4031x; 1.1654x over previous
#include <cuda_runtime.h>
#include <cuda_bf16.h>
#include <cstdint>

typedef unsigned long long u64;
typedef unsigned int u32;

#define NTHREADS 256
#define TPB      64
#define IN_DIM   256
#define HDIM     64
#define NEXP     12

// ---- smem byte offsets (per CTA, ~100KB total -> 2 CTAs/SM) ----
#define XH_OFF   0                       // X hi A-frags: [4mt][16kt][32][16B] = 32KB
#define XL_OFF   32768
#define H1H_OFF  65536                   // h1 hi frags: [4mt][4kt][32][16B] = 8KB
#define H1L_OFF  73728
#define H2H_OFF  81920
#define H2L_OFF  90112
#define GS_OFF   98304                   // gates [64][17] fp32 = 4352B
#define SMEM_BYTES (98304 + 64*17*4)     // 102656

// ---- precomputed B fragments (u64 = {reg0,reg1} per lane) ----
// W1: [e][16kt][8nt][2part][32lane] ; W2/W3: [e][4kt][8nt][2part][32lane]
__device__ u64 g_W1f[NEXP * 16 * 8 * 2 * 32];
__device__ u64 g_W2f[NEXP * 4 * 8 * 2 * 32];
__device__ u64 g_W3f[NEXP * 4 * 8 * 2 * 32];

// ============================ helpers ============================
__device__ __forceinline__ u32 sm_addr(const void* p) {
    return (u32)__cvta_generic_to_shared(p);
}
__device__ __host__ __forceinline__ u32 packbf_h(float v0, float v1) {
#ifdef __CUDA_ARCH__
    u32 r; asm("cvt.rn.bf16x2.f32 %0, %1, %2;" : "=r"(r) : "f"(v1), "f"(v0)); return r;
#else
    return 0;
#endif
}
__device__ __forceinline__ void split_bf(float x, float& h, float& l) {
    h = __bfloat162float(__float2bfloat16_rn(x));
    l = x - h;
}
__device__ __forceinline__ void mma_bf16(float* d, const u32* a, u64 b) {
    u32 b0 = (u32)b, b1 = (u32)(b >> 32);
    asm("mma.sync.aligned.m16n8k16.row.col.f32.bf16.bf16.f32 "
        "{%0,%1,%2,%3},{%4,%5,%6,%7},{%8,%9},{%0,%1,%2,%3};"
        : "+f"(d[0]), "+f"(d[1]), "+f"(d[2]), "+f"(d[3])
        : "r"(a[0]), "r"(a[1]), "r"(a[2]), "r"(a[3]), "r"(b0), "r"(b1));
}
__device__ __forceinline__ void lds128(u32* r, u32 a) {
    asm("ld.shared.v4.b32 {%0,%1,%2,%3},[%4];"
        : "=r"(r[0]), "=r"(r[1]), "=r"(r[2]), "=r"(r[3]) : "r"(a));
}
__device__ __forceinline__ void sts128(u32 a, const u32* r) {
    asm volatile("st.shared.v4.b32 [%0],{%1,%2,%3,%4};"
        :: "r"(a), "r"(r[0]), "r"(r[1]), "r"(r[2]), "r"(r[3]));
}

// ============================ prep kernel ============================
__global__ void prep_kernel(const float* __restrict__ Wt1, const float* __restrict__ Wt2,
                            const float* __restrict__ Wt3, const float* __restrict__ Ws1,
                            const float* __restrict__ Ws2, const float* __restrict__ Ws3) {
    int idx = blockIdx.x * blockDim.x + threadIdx.x;
    const float* W; u32* dst; int e, r;
    if (idx < NEXP * 16384) {
        e = idx >> 14; r = idx & 16383;
        W = (e < 8) ? Wt1 + e * 16384 : Ws1 + (e - 8) * 16384;
        dst = (u32*)g_W1f + e * 16384;
    } else if (idx < NEXP * 16384 + NEXP * 4096) {
        int i2 = idx - NEXP * 16384;
        e = i2 >> 12; r = i2 & 4095;
        W = (e < 8) ? Wt2 + e * 4096 : Ws2 + (e - 8) * 4096;
        dst = (u32*)g_W2f + e * 4096;
    } else if (idx < NEXP * 16384 + 2 * NEXP * 4096) {
        int i2 = idx - NEXP * 16384 - NEXP * 4096;
        e = i2 >> 12; r = i2 & 4095;
        W = (e < 8) ? Wt3 + e * 4096 : Ws3 + (e - 8) * 4096;
        dst = (u32*)g_W3f + e * 4096;
    } else return;
    int reg  = r & 1;
    int lane = (r >> 1) & 31;
    int part = (r >> 6) & 1;
    int nt   = (r >> 7) & 7;
    int kt   = r >> 10;
    int k0 = kt * 16 + reg * 8 + 2 * (lane & 3);
    int n  = nt * 8 + (lane >> 2);
    float w0 = W[k0 * 64 + n];
    float w1 = W[(k0 + 1) * 64 + n];
    float h0, l0, h1, l1;
    split_bf(w0, h0, l0); split_bf(w1, h1, l1);
    dst[r] = part ? packbf_h(l0, l1) : packbf_h(h0, h1);
}

// ============================ main kernel ============================
__global__ void __launch_bounds__(NTHREADS, 2)
mmoe_mma(const float* __restrict__ X,
         const float* __restrict__ bt1, const float* __restrict__ bt2,
         const float* __restrict__ bt3, const float* __restrict__ bs1,
         const float* __restrict__ bs2, const float* __restrict__ bs3,
         const float* __restrict__ Wg,  const float* __restrict__ bg,
         float* __restrict__ out)
{
    extern __shared__ char sm[];
    float* smf = (float*)sm;
    const int tid  = threadIdx.x;
    const int blk  = blockIdx.x;
    const int lane = tid & 31;
    const int w    = tid >> 5;
    const int wm   = w >> 2;      // 0..1 -> rows wm*32
    const int wn   = w & 3;       // 0..3 -> cols wn*16
    const u32 sb   = sm_addr(sm);

    // ---- stage Wg (16KB) into X-frag region temporarily, compute gates ----
    for (int i = tid; i < 4096 / 4; i += NTHREADS)
        ((float4*)smf)[i] = ((const float4*)Wg)[i];
    __syncthreads();
    if (tid < TPB * 2) {
        int tok = tid >> 1, t = tid & 1;
        const float* xr  = X + ((size_t)blk * TPB + tok) * IN_DIM;
        const float* wgt = smf + t * (IN_DIM * 8);
        float lg[8];
        #pragma unroll
        for (int j = 0; j < 8; j++) lg[j] = 0.f;
        #pragma unroll 4
        for (int k = 0; k < IN_DIM; k++) {
            float x = __ldg(xr + k);
            float4 w0 = *(const float4*)&wgt[k * 8];
            float4 w1 = *(const float4*)&wgt[k * 8 + 4];
            lg[0] = fmaf(x, w0.x, lg[0]); lg[1] = fmaf(x, w0.y, lg[1]);
            lg[2] = fmaf(x, w0.z, lg[2]); lg[3] = fmaf(x, w0.w, lg[3]);
            lg[4] = fmaf(x, w1.x, lg[4]); lg[5] = fmaf(x, w1.y, lg[5]);
            lg[6] = fmaf(x, w1.z, lg[6]); lg[7] = fmaf(x, w1.w, lg[7]);
        }
        float m = -1e30f;
        #pragma unroll
        for (int j = 0; j < 8; j++) { lg[j] += __ldg(bg + t * 8 + j); m = fmaxf(m, lg[j]); }
        float s = 0.f;
        #pragma unroll
        for (int j = 0; j < 8; j++) { lg[j] = expf(lg[j] - m); s += lg[j]; }
        float inv = 1.f / s;
        float* gsp = (float*)(sm + GS_OFF) + tok * 17 + t * 8;
        #pragma unroll
        for (int j = 0; j < 8; j++) gsp[j] = lg[j] * inv;
    }
    __syncthreads();

    // ---- convert X -> hi/lo A-fragments in smem ----
    // 4 mtiles x 16 ktiles x 32 lanes = 2048 frag slots
    {
        const float* Xb = X + (size_t)blk * TPB * IN_DIM;
        for (int i = tid; i < 4 * 16 * 32; i += NTHREADS) {
            int ln = i & 31, kt = (i >> 5) & 15, mt = i >> 9;
            int row = mt * 16 + (ln >> 2);
            int k   = kt * 16 + 2 * (ln & 3);
            float2 e0 = __ldg((const float2*)&Xb[row * IN_DIM + k]);
            float2 e1 = __ldg((const float2*)&Xb[(row + 8) * IN_DIM + k]);
            float2 e2 = __ldg((const float2*)&Xb[row * IN_DIM + k + 8]);
            float2 e3 = __ldg((const float2*)&Xb[(row + 8) * IN_DIM + k + 8]);
            float h0a,l0a,h0b,l0b, h1a,l1a,h1b,l1b;
            float h2a,l2a,h2b,l2b, h3a,l3a,h3b,l3b;
            split_bf(e0.x,h0a,l0a); split_bf(e0.y,h0b,l0b);
            split_bf(e1.x,h1a,l1a); split_bf(e1.y,h1b,l1b);
            split_bf(e2.x,h2a,l2a); split_bf(e2.y,h2b,l2b);
            split_bf(e3.x,h3a,l3a); split_bf(e3.y,h3b,l3b);
            u32 hi[4] = { packbf_h(h0a,h0b), packbf_h(h1a,h1b),
                          packbf_h(h2a,h2b), packbf_h(h3a,h3b) };
            u32 lo[4] = { packbf_h(l0a,l0b), packbf_h(l1a,l1b),
                          packbf_h(l2a,l2b), packbf_h(l3a,l3b) };
            sts128(sb + XH_OFF + i * 16, hi);
            sts128(sb + XL_OFF + i * 16, lo);
        }
    }
    __syncthreads();

    float oacc[2][2][2][4];     // [task][mt][nt][reg]
    #pragma unroll
    for (int t = 0; t < 2; t++)
        #pragma unroll
        for (int mt = 0; mt < 2; mt++)
            #pragma unroll
            for (int nt = 0; nt < 2; nt++)
                #pragma unroll
                for (int q = 0; q < 4; q++) oacc[t][mt][nt][q] = 0.f;

    const float* gsr = (const float*)(sm + GS_OFF);

    #pragma unroll 1
    for (int e = 0; e < NEXP; e++) {
        const u64* B1 = g_W1f + e * (16 * 8 * 2 * 32);
        const u64* B2 = g_W2f + e * (4 * 8 * 2 * 32);
        const u64* B3 = g_W3f + e * (4 * 8 * 2 * 32);
        const float* b1 = (e < 8) ? bt1 + e * 64 : bs1 + (e - 8) * 64;
        const float* b2 = (e < 8) ? bt2 + e * 64 : bs2 + (e - 8) * 64;
        const float* b3 = (e < 8) ? bt3 + e * 64 : bs3 + (e - 8) * 64;

        float acc[2][2][4];     // [mt][nt][reg]

        // ================= Layer 1 (K=256, 16 ktiles) =================
        #pragma unroll
        for (int mt = 0; mt < 2; mt++)
            #pragma unroll
            for (int nt = 0; nt < 2; nt++)
                #pragma unroll
                for (int q = 0; q < 4; q++) acc[mt][nt][q] = 0.f;

        #pragma unroll 2
        for (int kt = 0; kt < 16; kt++) {
            u32 ah[2][4], al[2][4];
            #pragma unroll
            for (int mt = 0; mt < 2; mt++) {
                u32 off = (u32)((((wm * 2 + mt) * 16 + kt) * 32 + lane) * 16);
                lds128(ah[mt], sb + XH_OFF + off);
                lds128(al[mt], sb + XL_OFF + off);
            }
            u64 bh[2], bl[2];
            #pragma unroll
            for (int nt = 0; nt < 2; nt++) {
                int bidx = ((kt * 8 + wn * 2 + nt) * 2) * 32 + lane;
                bh[nt] = __ldg(B1 + bidx);
                bl[nt] = __ldg(B1 + bidx + 32);
            }
            #pragma unroll
            for (int nt = 0; nt < 2; nt++) {
                mma_bf16(acc[0][nt], ah[0], bh[nt]);
                mma_bf16(acc[1][nt], ah[1], bh[nt]);
            }
            #pragma unroll
            for (int nt = 0; nt < 2; nt++) {
                mma_bf16(acc[0][nt], al[0], bh[nt]);
                mma_bf16(acc[1][nt], al[1], bh[nt]);
            }
            #pragma unroll
            for (int nt = 0; nt < 2; nt++) {
                mma_bf16(acc[0][nt], ah[0], bl[nt]);
                mma_bf16(acc[1][nt], ah[1], bl[nt]);
            }
        }
        // epilogue -> h1 frags (warp's 16 cols = ktile index wn of layer 2)
        #pragma unroll
        for (int mt = 0; mt < 2; mt++) {
            u32 hi[4], lo[4];
            #pragma unroll
            for (int nt = 0; nt < 2; nt++) {
                int col = wn * 16 + nt * 8 + 2 * (lane & 3);
                float2 bb = __ldg((const float2*)&b1[col]);
                float v0 = fmaxf(acc[mt][nt][0] + bb.x, 0.f);
                float v1 = fmaxf(acc[mt][nt][1] + bb.y, 0.f);
                float v2 = fmaxf(acc[mt][nt][2] + bb.x, 0.f);
                float v3 = fmaxf(acc[mt][nt][3] + bb.y, 0.f);
                float h0,l0,h1,l1,h2,l2,h3,l3;
                split_bf(v0,h0,l0); split_bf(v1,h1,l1);
                split_bf(v2,h2,l2); split_bf(v3,h3,l3);
                hi[nt * 2]     = packbf_h(h0, h1);
                hi[nt * 2 + 1] = packbf_h(h2, h3);
                lo[nt * 2]     = packbf_h(l0, l1);
                lo[nt * 2 + 1] = packbf_h(l2, l3);
            }
            u32 off = (u32)((((wm * 2 + mt) * 4 + wn) * 32 + lane) * 16);
            sts128(sb + H1H_OFF + off, hi);
            sts128(sb + H1L_OFF + off, lo);
        }
        __syncthreads();

        // ================= Layer 2 (K=64, 4 ktiles) =================
        #pragma unroll
        for (int mt = 0; mt < 2; mt++)
            #pragma unroll
            for (int nt = 0; nt < 2; nt++)
                #pragma unroll
                for (int q = 0; q < 4; q++) acc[mt][nt][q] = 0.f;
        #pragma unroll
        for (int kt = 0; kt < 4; kt++) {
            u32 ah[2][4], al[2][4];
            #pragma unroll
            for (int mt = 0; mt < 2; mt++) {
                u32 off = (u32)((((wm * 2 + mt) * 4 + kt) * 32 + lane) * 16);
                lds128(ah[mt], sb + H1H_OFF + off);
                lds128(al[mt], sb + H1L_OFF + off);
            }
            u64 bh[2], bl[2];
            #pragma unroll
            for (int nt = 0; nt < 2; nt++) {
                int bidx = ((kt * 8 + wn * 2 + nt) * 2) * 32 + lane;
                bh[nt] = __ldg(B2 + bidx);
                bl[nt] = __ldg(B2 + bidx + 32);
            }
            #pragma unroll
            for (int nt = 0; nt < 2; nt++) {
                mma_bf16(acc[0][nt], ah[0], bh[nt]);
                mma_bf16(acc[1][nt], ah[1], bh[nt]);
            }
            #pragma unroll
            for (int nt = 0; nt < 2; nt++) {
                mma_bf16(acc[0][nt], al[0], bh[nt]);
                mma_bf16(acc[1][nt], al[1], bh[nt]);
            }
            #pragma unroll
            for (int nt = 0; nt < 2; nt++) {
                mma_bf16(acc[0][nt], ah[0], bl[nt]);
                mma_bf16(acc[1][nt], ah[1], bl[nt]);
            }
        }
        #pragma unroll
        for (int mt = 0; mt < 2; mt++) {
            u32 hi[4], lo[4];
            #pragma unroll
            for (int nt = 0; nt < 2; nt++) {
                int col = wn * 16 + nt * 8 + 2 * (lane & 3);
                float2 bb = __ldg((const float2*)&b2[col]);
                float v0 = fmaxf(acc[mt][nt][0] + bb.x, 0.f);
                float v1 = fmaxf(acc[mt][nt][1] + bb.y, 0.f);
                float v2 = fmaxf(acc[mt][nt][2] + bb.x, 0.f);
                float v3 = fmaxf(acc[mt][nt][3] + bb.y, 0.f);
                float h0,l0,h1,l1,h2,l2,h3,l3;
                split_bf(v0,h0,l0); split_bf(v1,h1,l1);
                split_bf(v2,h2,l2); split_bf(v3,h3,l3);
                hi[nt * 2]     = packbf_h(h0, h1);
                hi[nt * 2 + 1] = packbf_h(h2, h3);
                lo[nt * 2]     = packbf_h(l0, l1);
                lo[nt * 2 + 1] = packbf_h(l2, l3);
            }
            u32 off = (u32)((((wm * 2 + mt) * 4 + wn) * 32 + lane) * 16);
            sts128(sb + H2H_OFF + off, hi);
            sts128(sb + H2L_OFF + off, lo);
        }
        __syncthreads();

        // ================= Layer 3 (K=64) + gated combine =================
        #pragma unroll
        for (int mt = 0; mt < 2; mt++)
            #pragma unroll
            for (int nt = 0; nt < 2; nt++)
                #pragma unroll
                for (int q = 0; q < 4; q++) acc[mt][nt][q] = 0.f;
        #pragma unroll
        for (int kt = 0; kt < 4; kt++) {
            u32 ah[2][4], al[2][4];
            #pragma unroll
            for (int mt = 0; mt < 2; mt++) {
                u32 off = (u32)((((wm * 2 + mt) * 4 + kt) * 32 + lane) * 16);
                lds128(ah[mt], sb + H2H_OFF + off);
                lds128(al[mt], sb + H2L_OFF + off);
            }
            u64 bh[2], bl[2];
            #pragma unroll
            for (int nt = 0; nt < 2; nt++) {
                int bidx = ((kt * 8 + wn * 2 + nt) * 2) * 32 + lane;
                bh[nt] = __ldg(B3 + bidx);
                bl[nt] = __ldg(B3 + bidx + 32);
            }
            #pragma unroll
            for (int nt = 0; nt < 2; nt++) {
                mma_bf16(acc[0][nt], ah[0], bh[nt]);
                mma_bf16(acc[1][nt], ah[1], bh[nt]);
            }
            #pragma unroll
            for (int nt = 0; nt < 2; nt++) {
                mma_bf16(acc[0][nt], al[0], bh[nt]);
                mma_bf16(acc[1][nt], al[1], bh[nt]);
            }
            #pragma unroll
            for (int nt = 0; nt < 2; nt++) {
                mma_bf16(acc[0][nt], ah[0], bl[nt]);
                mma_bf16(acc[1][nt], ah[1], bl[nt]);
            }
        }
        // gates: 4 rows per thread (2 mt x {r, r+8})
        float g0r[2][2], g1r[2][2];
        #pragma unroll
        for (int mt = 0; mt < 2; mt++) {
            #pragma unroll
            for (int rh = 0; rh < 2; rh++) {
                int row = wm * 32 + mt * 16 + (lane >> 2) + rh * 8;
                float a, b;
                if (e < 8) {
                    int t = e >> 2, ix = e & 3;
                    float g = gsr[row * 17 + t * 8 + ix];
                    a = t ? 0.f : g;
                    b = t ? g : 0.f;
                } else {
                    int sx = e - 8;
                    a = gsr[row * 17 + 4 + sx];
                    b = gsr[row * 17 + 12 + sx];
                }
                g0r[mt][rh] = a; g1r[mt][rh] = b;
            }
        }
        #pragma unroll
        for (int mt = 0; mt < 2; mt++) {
            #pragma unroll
            for (int nt = 0; nt < 2; nt++) {
                int col = wn * 16 + nt * 8 + 2 * (lane & 3);
                float2 bb = __ldg((const float2*)&b3[col]);
                float v0 = acc[mt][nt][0] + bb.x;
                float v1 = acc[mt][nt][1] + bb.y;
                float v2 = acc[mt][nt][2] + bb.x;
                float v3 = acc[mt][nt][3] + bb.y;
                oacc[0][mt][nt][0] = fmaf(g0r[mt][0], v0, oacc[0][mt][nt][0]);
                oacc[0][mt][nt][1] = fmaf(g0r[mt][0], v1, oacc[0][mt][nt][1]);
                oacc[0][mt][nt][2] = fmaf(g0r[mt][1], v2, oacc[0][mt][nt][2]);
                oacc[0][mt][nt][3] = fmaf(g0r[mt][1], v3, oacc[0][mt][nt][3]);
                oacc[1][mt][nt][0] = fmaf(g1r[mt][0], v0, oacc[1][mt][nt][0]);
                oacc[1][mt][nt][1] = fmaf(g1r[mt][0], v1, oacc[1][mt][nt][1]);
                oacc[1][mt][nt][2] = fmaf(g1r[mt][1], v2, oacc[1][mt][nt][2]);
                oacc[1][mt][nt][3] = fmaf(g1r[mt][1], v3, oacc[1][mt][nt][3]);
            }
        }
        __syncthreads();
    }

    // ---- write output [B, 2, 64] ----
    float* ob = out + (size_t)blk * TPB * 128;
    #pragma unroll
    for (int t = 0; t < 2; t++) {
        #pragma unroll
        for (int mt = 0; mt < 2; mt++) {
            #pragma unroll
            for (int rh = 0; rh < 2; rh++) {
                int row = wm * 32 + mt * 16 + (lane >> 2) + rh * 8;
                #pragma unroll
                for (int nt = 0; nt < 2; nt++) {
                    int col = wn * 16 + nt * 8 + 2 * (lane & 3);
                    float2 v = make_float2(oacc[t][mt][nt][rh * 2],
                                           oacc[t][mt][nt][rh * 2 + 1]);
                    *(float2*)&ob[row * 128 + t * 64 + col] = v;
                }
            }
        }
    }
}

// ============================ launch ============================
extern "C" void kernel_launch(void* const* d_in, const int* in_sizes, int n_in,
                              void* d_out, int out_size) {
    const float* X   = (const float*)d_in[0];
    const float* Wt1 = (const float*)d_in[1];
    const float* bt1 = (const float*)d_in[2];
    const float* Wt2 = (const float*)d_in[3];
    const float* bt2 = (const float*)d_in[4];
    const float* Wt3 = (const float*)d_in[5];
    const float* bt3 = (const float*)d_in[6];
    const float* Ws1 = (const float*)d_in[7];
    const float* bs1 = (const float*)d_in[8];
    const float* Ws2 = (const float*)d_in[9];
    const float* bs2 = (const float*)d_in[10];
    const float* Ws3 = (const float*)d_in[11];
    const float* bs3 = (const float*)d_in[12];
    const float* Wg  = (const float*)d_in[13];
    const float* bg  = (const float*)d_in[14];
    float* out = (float*)d_out;

    int B = in_sizes[0] / IN_DIM;          // 65536
    int grid = B / TPB;                    // 1024

    int prep_total = NEXP * 16384 + 2 * NEXP * 4096;   // 294912
    prep_kernel<<<(prep_total + 255) / 256, 256>>>(Wt1, Wt2, Wt3, Ws1, Ws2, Ws3);

    cudaFuncSetAttribute(mmoe_mma, cudaFuncAttributeMaxDynamicSharedMemorySize, SMEM_BYTES);
    mmoe_mma<<<grid, NTHREADS, SMEM_BYTES>>>(
        X, bt1, bt2, bt3, bs1, bs2, bs3, Wg, bg, out);
}